// round 4
// baseline (speedup 1.0000x reference)
#include <cuda_runtime.h>
#include <cuda_bf16.h>

#define EPS 1e-5f

// Scratch (device globals: allocation-free)
__device__ float g_a[256 * 32];     // a = x@W1 + b1
__device__ float g_s[256];          // row sums of a
__device__ float g_q[256];          // row sums of a^2
__device__ float g_U[256 * 1024];   // U[i, e*32+o] = sum_d a[i,d]*gamma[d*32+e]*W2[(d*32+e)*32+o]
__device__ float g_c[32];           // c[o] = sum_k gamma[k]*W2[k,o]
__device__ float g_t[32];           // t[o] = sum_k beta[k]*W2[k,o] + b2[o]

// Kernel 1: a = x@W1 + b1, per-row sum s and sumsq q; block 256 computes c,t.
__global__ void k1_proj_stats(const float* __restrict__ x,
                              const float* __restrict__ W1,
                              const float* __restrict__ b1,
                              const float* __restrict__ gamma,
                              const float* __restrict__ beta,
                              const float* __restrict__ W2,
                              const float* __restrict__ b2) {
    int blk = blockIdx.x;
    int tid = threadIdx.x;
    if (blk < 256) {
        __shared__ float xs[256];
        __shared__ float red[8][32];
        xs[tid] = x[blk * 256 + tid];
        __syncthreads();
        int h = tid & 31;
        int chunk = tid >> 5;          // 8 chunks of 32 c-values
        int c0 = chunk * 32;
        float p = 0.f;
#pragma unroll
        for (int c = 0; c < 32; c++) p += xs[c0 + c] * W1[(c0 + c) * 32 + h];
        red[chunk][h] = p;
        __syncthreads();
        if (tid < 32) {
            float av = b1[h];
#pragma unroll
            for (int k = 0; k < 8; k++) av += red[k][h];
            g_a[blk * 32 + h] = av;
            float s = av, q = av * av;
#pragma unroll
            for (int off = 16; off; off >>= 1) {
                s += __shfl_down_sync(0xffffffffu, s, off);
                q += __shfl_down_sync(0xffffffffu, q, off);
            }
            if (h == 0) { g_s[blk] = s; g_q[blk] = q; }
        }
    } else {
        // c[o], t[o]
        __shared__ float rc[8][32], rt[8][32];
        int o = tid & 31;
        int grp = tid >> 5;           // 8 groups x 128 k each
        float pc = 0.f, pt = 0.f;
        int k0 = grp * 128;
        for (int k = k0; k < k0 + 128; k++) {
            float w = W2[k * 32 + o];
            pc += gamma[k] * w;
            pt += beta[k] * w;
        }
        rc[grp][o] = pc;
        rt[grp][o] = pt;
        __syncthreads();
        if (tid < 32) {
            float cc = 0.f, tt = b2[o];
#pragma unroll
            for (int k = 0; k < 8; k++) { cc += rc[k][o]; tt += rt[k][o]; }
            g_c[o] = cc;
            g_t[o] = tt;
        }
    }
}

// Kernel 2: U[i, col] = sum_d a[i,d] * gamma[d*32+e] * W2[(d*32+e)*32+o], col = e*32+o.
// grid = (8 eo-tiles of 128, 16 i-tiles of 16), 256 threads.
__global__ void k2_U(const float* __restrict__ gamma,
                     const float* __restrict__ W2) {
    __shared__ float as[16][32];
    int tid = threadIdx.x;
    // load A tile: 512 floats
    {
        int idx = tid;
        as[idx >> 5][idx & 31] = g_a[blockIdx.y * 512 + idx];
        idx += 256;
        as[idx >> 5][idx & 31] = g_a[blockIdx.y * 512 + idx];
    }
    __syncthreads();

    int col = blockIdx.x * 128 + (tid & 127);
    int e = col >> 5;
    int o = col & 31;
    float g[32];
#pragma unroll
    for (int d = 0; d < 32; d++)
        g[d] = gamma[d * 32 + e] * W2[(d * 32 + e) * 32 + o];

    int i0 = blockIdx.y * 16;
    for (int ii = tid >> 7; ii < 16; ii += 2) {
        float acc = 0.f;
#pragma unroll
        for (int d = 0; d < 32; d++) acc += as[ii][d] * g[d];
        g_U[(i0 + ii) * 1024 + col] = acc;
    }
}

// Kernel 3: out[i,j,o] = r_ij * (sum_e U[i,e,o]*a[j,e] - mu_ij*c[o]) + t[o]
// grid = (16 j-tiles of 16, 32 i-tiles of 8), 512 threads = 16 j x 32 o.
#define K3_ITILE 8
#define K3_JTILE 16
__global__ void k3_out(float* __restrict__ out) {
    __shared__ float Us[K3_ITILE * 1024];   // 32 KB
    __shared__ float ss[K3_ITILE], qs[K3_ITILE];
    int tid = threadIdx.x;                  // 512
    int i0 = blockIdx.y * K3_ITILE;
    int j0 = blockIdx.x * K3_JTILE;

#pragma unroll
    for (int k = 0; k < K3_ITILE * 1024 / 512; k++)
        Us[tid + k * 512] = g_U[i0 * 1024 + tid + k * 512];
    if (tid < K3_ITILE) { ss[tid] = g_s[i0 + tid]; qs[tid] = g_q[i0 + tid]; }
    __syncthreads();

    int o = tid & 31;
    int jj = tid >> 5;                      // 0..15
    int j = j0 + jj;

    float aj[32];
#pragma unroll
    for (int e = 0; e < 32; e++) aj[e] = g_a[j * 32 + e];
    float sj = g_s[j], qj = g_q[j];
    float co = g_c[o], to = g_t[o];
    const float inv = 1.0f / 1024.0f;

#pragma unroll
    for (int ii = 0; ii < K3_ITILE; ii++) {
        float acc = 0.f;
        const float* up = &Us[ii * 1024 + o];
#pragma unroll
        for (int e = 0; e < 32; e++) acc += aj[e] * up[e * 32];
        float mu = ss[ii] * sj * inv;
        float var = qs[ii] * qj * inv - mu * mu;
        float r = rsqrtf(var + EPS);
        out[((size_t)(i0 + ii) * 256 + j) * 32 + o] = r * (acc - mu * co) + to;
    }
}

extern "C" void kernel_launch(void* const* d_in, const int* in_sizes, int n_in,
                              void* d_out, int out_size) {
    const float* x     = (const float*)d_in[0];
    const float* W1    = (const float*)d_in[1];
    const float* b1    = (const float*)d_in[2];
    const float* gamma = (const float*)d_in[3];
    const float* beta  = (const float*)d_in[4];
    const float* W2    = (const float*)d_in[5];
    const float* b2    = (const float*)d_in[6];
    float* out = (float*)d_out;

    k1_proj_stats<<<257, 256>>>(x, W1, b1, gamma, beta, W2, b2);
    k2_U<<<dim3(8, 16), 256>>>(gamma, W2);
    k3_out<<<dim3(16, 32), 512>>>(out);
}

// round 5
// speedup vs baseline: 1.6224x; 1.6224x over previous
#include <cuda_runtime.h>
#include <cuda_bf16.h>

#define EPS 1e-5f

// Scratch (device globals: allocation-free)
__device__ float g_a[256 * 32];     // a = x@W1 + b1
__device__ float g_s[256];          // row sums of a
__device__ float g_q[256];          // row sums of a^2
__device__ float g_U[256 * 1024];   // U[i, e*32+o] = sum_d a[i,d]*gamma[d*32+e]*W2[(d*32+e)*32+o]
__device__ float g_c[32];           // c[o] = sum_k gamma[k]*W2[k,o]
__device__ float g_t[32];           // t[o] = sum_k beta[k]*W2[k,o] + b2[o]

// Kernel A (fused former k1+k2):
// blocks 0..127: it = bx>>2 (8-row i-tile), ct = bx&3 (256-col U tile).
//   Each block computes a for its 8 rows (c-split partials, register-reused W1),
//   then 256 U columns. ct==0 blocks also publish g_a/g_s/g_q.
// block 128: c[o], t[o].
__global__ __launch_bounds__(256) void kA(const float* __restrict__ x,
                                          const float* __restrict__ W1,
                                          const float* __restrict__ b1,
                                          const float* __restrict__ gamma,
                                          const float* __restrict__ beta,
                                          const float* __restrict__ W2,
                                          const float* __restrict__ b2) {
    int bx = blockIdx.x;
    int tid = threadIdx.x;

    if (bx == 128) {
        __shared__ float rc[8][32], rt[8][32];
        int o = tid & 31, grp = tid >> 5;
        float pc = 0.f, pt = 0.f;
        int k0 = grp * 128;
#pragma unroll 8
        for (int k = k0; k < k0 + 128; k++) {
            float w = W2[k * 32 + o];
            pc += gamma[k] * w;
            pt += beta[k] * w;
        }
        rc[grp][o] = pc;
        rt[grp][o] = pt;
        __syncthreads();
        if (tid < 32) {
            float cc = 0.f, tt = b2[o];
#pragma unroll
            for (int g = 0; g < 8; g++) { cc += rc[g][o]; tt += rt[g][o]; }
            g_c[o] = cc;
            g_t[o] = tt;
        }
        return;
    }

    int it = bx >> 2, ct = bx & 3;
    int i0 = it * 8;

    __shared__ __align__(16) float xs[8 * 256];   // 8 KB x tile
    __shared__ float red[8][8][32];               // 8 KB partials [grp][r][h]
    __shared__ float as_[8][32];                  // a tile

    // Load x rows i0..i0+7 (2048 floats) via float4
    {
        const float4* xp = (const float4*)(x + i0 * 256);
        float4* sp = (float4*)xs;
        sp[tid]       = xp[tid];
        sp[tid + 256] = xp[tid + 256];
    }
    __syncthreads();

    // a partials: thread (h = lane, grp = warp) covers c in [grp*32, grp*32+32)
    int h = tid & 31, grp = tid >> 5;
    {
        float acc[8];
#pragma unroll
        for (int r = 0; r < 8; r++) acc[r] = 0.f;
#pragma unroll
        for (int cc = 0; cc < 8; cc++) {
            int c = grp * 32 + cc * 4;
            float w0 = W1[(c + 0) * 32 + h];
            float w1 = W1[(c + 1) * 32 + h];
            float w2 = W1[(c + 2) * 32 + h];
            float w3 = W1[(c + 3) * 32 + h];
#pragma unroll
            for (int r = 0; r < 8; r++) {
                float4 xv = *(const float4*)&xs[r * 256 + c];
                acc[r] += xv.x * w0 + xv.y * w1 + xv.z * w2 + xv.w * w3;
            }
        }
#pragma unroll
        for (int r = 0; r < 8; r++) red[grp][r][h] = acc[r];
    }
    __syncthreads();

    // Reduce partials -> a; publish a/s/q (ct==0 only)
    {
        int r = tid >> 5;
        float a = b1[h];
#pragma unroll
        for (int g = 0; g < 8; g++) a += red[g][r][h];
        as_[r][h] = a;
        if (ct == 0) g_a[(i0 + r) * 32 + h] = a;
        float s = a, q = a * a;
#pragma unroll
        for (int off = 16; off; off >>= 1) {
            s += __shfl_down_sync(0xffffffffu, s, off);
            q += __shfl_down_sync(0xffffffffu, q, off);
        }
        if (ct == 0 && h == 0) { g_s[i0 + r] = s; g_q[i0 + r] = q; }
    }
    __syncthreads();

    // U: one column per thread (col = ct*256 + tid), coalesced stores
    {
        int col = ct * 256 + tid;
        int e = col >> 5, o = col & 31;
        float g[32];
#pragma unroll
        for (int d = 0; d < 32; d++)
            g[d] = gamma[d * 32 + e] * W2[(d * 32 + e) * 32 + o];
#pragma unroll
        for (int r = 0; r < 8; r++) {
            float acc2 = 0.f;
#pragma unroll
            for (int d = 0; d < 32; d++) acc2 += as_[r][d] * g[d];
            g_U[(i0 + r) * 1024 + col] = acc2;
        }
    }
}

// Kernel 3: out[i,j,o] = r_ij * (sum_e U[i,e,o]*a[j,e] - mu_ij*c[o]) + t[o]
// Block: i-tile 8 x j-tile 16, 128 threads = 32 o x 4 jgrp; each thread owns 4 j
// with aj[4][32] in registers (4x FMA reuse per Us smem read).
__global__ __launch_bounds__(128) void k3_out(float* __restrict__ out) {
    __shared__ __align__(16) float Us[8 * 1024];   // 32 KB
    __shared__ __align__(16) float ajs[16 * 32];   // 2 KB
    __shared__ float ss[8], qs[8];

    int tid = threadIdx.x;
    int j0 = blockIdx.x * 16, i0 = blockIdx.y * 8;

    {
        const float4* up = (const float4*)(g_U + i0 * 1024);
        float4* sp = (float4*)Us;
#pragma unroll
        for (int k = 0; k < 16; k++) sp[tid + k * 128] = up[tid + k * 128];
        ((float4*)ajs)[tid] = ((const float4*)(g_a + j0 * 32))[tid];
        if (tid < 8) { ss[tid] = g_s[i0 + tid]; qs[tid] = g_q[i0 + tid]; }
    }
    __syncthreads();

    int o = tid & 31, jgrp = tid >> 5;

    float aj[4][32];
#pragma unroll
    for (int k = 0; k < 4; k++) {
#pragma unroll
        for (int e4 = 0; e4 < 8; e4++) {
            float4 v = *(const float4*)&ajs[(jgrp * 4 + k) * 32 + e4 * 4];
            aj[k][e4 * 4 + 0] = v.x;
            aj[k][e4 * 4 + 1] = v.y;
            aj[k][e4 * 4 + 2] = v.z;
            aj[k][e4 * 4 + 3] = v.w;
        }
    }
    float sj[4], qj[4];
#pragma unroll
    for (int k = 0; k < 4; k++) {
        int j = j0 + jgrp * 4 + k;
        sj[k] = g_s[j];
        qj[k] = g_q[j];
    }
    float co = g_c[o], to = g_t[o];
    const float inv = 1.0f / 1024.0f;

    for (int ii = 0; ii < 8; ii++) {
        float acc0 = 0.f, acc1 = 0.f, acc2 = 0.f, acc3 = 0.f;
        const float* up = &Us[ii * 1024 + o];
#pragma unroll
        for (int e = 0; e < 32; e++) {
            float u = up[e * 32];
            acc0 += u * aj[0][e];
            acc1 += u * aj[1][e];
            acc2 += u * aj[2][e];
            acc3 += u * aj[3][e];
        }
        float si = ss[ii], qi = qs[ii];
        size_t base = ((size_t)(i0 + ii) * 256 + j0 + jgrp * 4) * 32 + o;
        float accv[4] = {acc0, acc1, acc2, acc3};
#pragma unroll
        for (int k = 0; k < 4; k++) {
            float mu = si * sj[k] * inv;
            float var = qi * qj[k] * inv - mu * mu;
            float r = rsqrtf(var + EPS);
            out[base + (size_t)k * 32] = r * (accv[k] - mu * co) + to;
        }
    }
}

extern "C" void kernel_launch(void* const* d_in, const int* in_sizes, int n_in,
                              void* d_out, int out_size) {
    const float* x     = (const float*)d_in[0];
    const float* W1    = (const float*)d_in[1];
    const float* b1    = (const float*)d_in[2];
    const float* gamma = (const float*)d_in[3];
    const float* beta  = (const float*)d_in[4];
    const float* W2    = (const float*)d_in[5];
    const float* b2    = (const float*)d_in[6];
    float* out = (float*)d_out;

    kA<<<129, 256>>>(x, W1, b1, gamma, beta, W2, b2);
    k3_out<<<dim3(16, 32), 128>>>(out);
}